// round 7
// baseline (speedup 1.0000x reference)
#include <cuda_runtime.h>
#include <math_constants.h>

// Batched nearest-neighbor argmin + gather (HBM-streaming).
//   y: [B,2] f32, Y_surf: [B,2,G] f32, U_grid: [2,G] f32, out: [B,2] f32
//   out[b,:] = U_grid[:, argmin_g ||Y_surf[b,:,g] - y[b,:]||^2]
//
// R6 base (block-per-sample, 128 thr, plain LDG float4, 4 independent argmin
// accumulators, packed-u64 reduction) + x4 load unroll: with G=2500 (n4=625)
// the main loop is exactly ONE iteration -> 8 independent LDG.128 front-
// batched per thread covering 80% of the stream, then one predicated tail.

#define NT 128

struct Acc { float d[4]; int g[4]; };

__device__ __forceinline__ void proc4(const float4& a, const float4& c, int g,
                                      float y0, float y1, Acc& acc) {
    float dx, dz, d;
    dx = a.x - y0; dz = c.x - y1; d = dx * dx + dz * dz;
    if (d < acc.d[0]) { acc.d[0] = d; acc.g[0] = g + 0; }
    dx = a.y - y0; dz = c.y - y1; d = dx * dx + dz * dz;
    if (d < acc.d[1]) { acc.d[1] = d; acc.g[1] = g + 1; }
    dx = a.z - y0; dz = c.z - y1; d = dx * dx + dz * dz;
    if (d < acc.d[2]) { acc.d[2] = d; acc.g[2] = g + 2; }
    dx = a.w - y0; dz = c.w - y1; d = dx * dx + dz * dz;
    if (d < acc.d[3]) { acc.d[3] = d; acc.g[3] = g + 3; }
}

__device__ __forceinline__ unsigned long long pack(float d, int g) {
    return ((unsigned long long)__float_as_uint(d) << 32) | (unsigned)g;
}

__global__ __launch_bounds__(NT)
void lqr_argmin_kernel(const float* __restrict__ y,
                       const float* __restrict__ Ys,
                       const float* __restrict__ Ug,
                       float* __restrict__ out,
                       int G) {
    const int b   = blockIdx.x;
    const int tid = threadIdx.x;

    const float y0 = y[2 * b + 0];
    const float y1 = y[2 * b + 1];

    const float4* __restrict__ v0 =
        reinterpret_cast<const float4*>(Ys + (size_t)b * 2 * G);
    const float4* __restrict__ v1 = v0 + (G >> 2);
    const int n4 = G >> 2;  // G % 4 == 0 (G = 2500 -> n4 = 625)

    Acc acc;
    #pragma unroll
    for (int k = 0; k < 4; k++) { acc.d[k] = CUDART_INF_F; acc.g[k] = 0; }

    int i = tid;
    // x4 unroll: 8 independent 128-bit loads front-batched per thread.
    // For n4=625, NT=128 this runs exactly once per thread.
    for (; i + 3 * NT < n4; i += 4 * NT) {
        float4 a0 = v0[i];
        float4 a1 = v0[i + NT];
        float4 a2 = v0[i + 2 * NT];
        float4 a3 = v0[i + 3 * NT];
        float4 c0 = v1[i];
        float4 c1 = v1[i + NT];
        float4 c2 = v1[i + 2 * NT];
        float4 c3 = v1[i + 3 * NT];
        proc4(a0, c0, (i)          << 2, y0, y1, acc);
        proc4(a1, c1, (i + NT)     << 2, y0, y1, acc);
        proc4(a2, c2, (i + 2 * NT) << 2, y0, y1, acc);
        proc4(a3, c3, (i + 3 * NT) << 2, y0, y1, acc);
    }
    // Tail: at most ceil((n4 mod 4*NT)/NT) iterations (1 for G=2500).
    for (; i < n4; i += NT) {
        float4 a = v0[i];
        float4 c = v1[i];
        proc4(a, c, i << 2, y0, y1, acc);
    }

    // Packed u64 min == (min d2, tie -> min idx) lexicographic; d2 >= 0 so
    // IEEE bits are order-monotone as u32 -> exact jnp.argmin semantics.
    unsigned long long best = pack(acc.d[0], acc.g[0]);
    #pragma unroll
    for (int k = 1; k < 4; k++) {
        unsigned long long o = pack(acc.d[k], acc.g[k]);
        if (o < best) best = o;
    }

    #pragma unroll
    for (int off = 16; off > 0; off >>= 1) {
        unsigned long long o = __shfl_down_sync(0xffffffffu, best, off);
        if (o < best) best = o;
    }

    __shared__ unsigned long long sb[NT / 32];
    const int w = tid >> 5;
    if ((tid & 31) == 0) sb[w] = best;
    __syncthreads();

    if (w == 0) {
        const int nw = NT / 32;
        best = (tid < nw) ? sb[tid] : 0xffffffffffffffffULL;
        #pragma unroll
        for (int off = 16; off > 0; off >>= 1) {
            unsigned long long o = __shfl_down_sync(0xffffffffu, best, off);
            if (o < best) best = o;
        }
        if (tid == 0) {
            const int bidx = (int)(unsigned)best;
            out[2 * b + 0] = Ug[bidx];
            out[2 * b + 1] = Ug[(size_t)G + bidx];
        }
    }
}

extern "C" void kernel_launch(void* const* d_in, const int* in_sizes, int n_in,
                              void* d_out, int out_size) {
    const float* y  = (const float*)d_in[0];   // [B, 2]
    const float* Ys = (const float*)d_in[1];   // [B, 2, G]
    const float* Ug = (const float*)d_in[2];   // [2, G]
    float* out = (float*)d_out;                // [B, 2]

    const int B = in_sizes[0] / 2;
    const int G = in_sizes[2] / 2;

    lqr_argmin_kernel<<<B, NT>>>(y, Ys, Ug, out, G);
}

// round 8
// speedup vs baseline: 1.0382x; 1.0382x over previous
#include <cuda_runtime.h>
#include <math_constants.h>

// Batched nearest-neighbor argmin + gather (HBM-streaming, ~83% DRAM).
//   y: [B,2] f32, Y_surf: [B,2,G] f32, U_grid: [2,G] f32, out: [B,2] f32
//   out[b,:] = U_grid[:, argmin_g ||Y_surf[b,:,g] - y[b,:]||^2]
//
// R6 config (best measured): block-per-sample, 128 thr, plain LDG float4,
// x2 unroll (MLP_p1=4 sweet spot; x4 regressed via L1tex-queue contention),
// 4 independent argmin accumulators. New: REDUX.MIN.U32-based reduction
// (2 ops/level instead of 10 u64 shuffles) with exact first-index tie-break
// (d2 >= 0 -> IEEE bits order-monotone as u32).

#define NT 128

struct Acc { float d[4]; int g[4]; };

__device__ __forceinline__ void proc4(const float4& a, const float4& c, int g,
                                      float y0, float y1, Acc& acc) {
    float dx, dz, d;
    dx = a.x - y0; dz = c.x - y1; d = dx * dx + dz * dz;
    if (d < acc.d[0]) { acc.d[0] = d; acc.g[0] = g + 0; }
    dx = a.y - y0; dz = c.y - y1; d = dx * dx + dz * dz;
    if (d < acc.d[1]) { acc.d[1] = d; acc.g[1] = g + 1; }
    dx = a.z - y0; dz = c.z - y1; d = dx * dx + dz * dz;
    if (d < acc.d[2]) { acc.d[2] = d; acc.g[2] = g + 2; }
    dx = a.w - y0; dz = c.w - y1; d = dx * dx + dz * dz;
    if (d < acc.d[3]) { acc.d[3] = d; acc.g[3] = g + 3; }
}

__global__ __launch_bounds__(NT)
void lqr_argmin_kernel(const float* __restrict__ y,
                       const float* __restrict__ Ys,
                       const float* __restrict__ Ug,
                       float* __restrict__ out,
                       int G) {
    const int b   = blockIdx.x;
    const int tid = threadIdx.x;

    const float y0 = y[2 * b + 0];
    const float y1 = y[2 * b + 1];

    const float4* __restrict__ v0 =
        reinterpret_cast<const float4*>(Ys + (size_t)b * 2 * G);
    const float4* __restrict__ v1 = v0 + (G >> 2);
    const int n4 = G >> 2;  // G % 4 == 0 (G = 2500)

    Acc acc;
    #pragma unroll
    for (int k = 0; k < 4; k++) { acc.d[k] = CUDART_INF_F; acc.g[k] = 0; }

    int i = tid;
    // x2 unroll: 4 independent 128-bit loads in flight per thread (MLP_p1=4).
    for (; i + NT < n4; i += 2 * NT) {
        float4 a0 = v0[i];
        float4 a1 = v0[i + NT];
        float4 c0 = v1[i];
        float4 c1 = v1[i + NT];
        proc4(a0, c0, i << 2,        y0, y1, acc);
        proc4(a1, c1, (i + NT) << 2, y0, y1, acc);
    }
    if (i < n4) {
        float4 a = v0[i];
        float4 c = v1[i];
        proc4(a, c, i << 2, y0, y1, acc);
    }

    // Thread-local merge: (min d2, tie -> min idx).
    float best = acc.d[0];
    int   bidx = acc.g[0];
    #pragma unroll
    for (int k = 1; k < 4; k++) {
        if (acc.d[k] < best || (acc.d[k] == best && acc.g[k] < bidx)) {
            best = acc.d[k]; bidx = acc.g[k];
        }
    }

    // Warp reduction via REDUX.MIN.U32 x2: min d2 bits, then min idx among
    // holders of the min (exact first-index tie-break).
    unsigned dbits = __float_as_uint(best);
    unsigned wmin  = __reduce_min_sync(0xffffffffu, dbits);
    unsigned icand = (dbits == wmin) ? (unsigned)bidx : 0xffffffffu;
    unsigned widx  = __reduce_min_sync(0xffffffffu, icand);

    __shared__ unsigned sd[NT / 32];
    __shared__ unsigned sg[NT / 32];
    const int w = tid >> 5;
    if ((tid & 31) == 0) { sd[w] = wmin; sg[w] = widx; }
    __syncthreads();

    if (w == 0) {
        const int nw = NT / 32;
        unsigned d2 = (tid < nw) ? sd[tid] : 0xffffffffu;
        unsigned ix = (tid < nw) ? sg[tid] : 0xffffffffu;
        unsigned bmin = __reduce_min_sync(0xffffffffu, d2);
        unsigned bc   = (d2 == bmin) ? ix : 0xffffffffu;
        unsigned bi   = __reduce_min_sync(0xffffffffu, bc);
        if (tid == 0) {
            out[2 * b + 0] = Ug[bi];
            out[2 * b + 1] = Ug[(size_t)G + bi];
        }
    }
}

extern "C" void kernel_launch(void* const* d_in, const int* in_sizes, int n_in,
                              void* d_out, int out_size) {
    const float* y  = (const float*)d_in[0];   // [B, 2]
    const float* Ys = (const float*)d_in[1];   // [B, 2, G]
    const float* Ug = (const float*)d_in[2];   // [2, G]
    float* out = (float*)d_out;                // [B, 2]

    const int B = in_sizes[0] / 2;
    const int G = in_sizes[2] / 2;

    lqr_argmin_kernel<<<B, NT>>>(y, Ys, Ug, out, G);
}